// round 1
// baseline (speedup 1.0000x reference)
#include <cuda_runtime.h>
#include <math.h>

#define DD     2048
#define NS     16
#define BB     2
#define LL     4096
#define NCHAN  (BB * DD)       // 4096 channels, one warp each
#define CHUNK  (LL / 32)       // 128 timesteps per lane

__global__ __launch_bounds__(256) void cema_kernel(
    const float* __restrict__ x,      // (B, D, L)
    const float* __restrict__ alpha,  // (D, N)
    const float* __restrict__ delta,  // (D, N)
    const float* __restrict__ theta,  // (D)
    const float* __restrict__ gamma,  // (D, N, 2)
    const float* __restrict__ omega,  // (D)
    float* __restrict__ out)          // y (B,D,L) then h (B,D,N,2)
{
    const int warp = (blockIdx.x * blockDim.x + threadIdx.x) >> 5;
    const int lane = threadIdx.x & 31;
    if (warp >= NCHAN) return;
    const int b = warp >> 11;          // warp / DD
    const int d = warp & (DD - 1);     // warp % DD

    // ---- per-channel coefficients (each lane computes all N redundantly;
    //      loads are warp-uniform -> broadcast from L1) ----
    float qr[NS], qi[NS], cr[NS], ci[NS];
    const float th   = theta[d];
    const float base = (1.0f / (1.0f + expf(-th))) * (6.283185307179586f / 16.0f);
    const float om   = omega[d];
    #pragma unroll
    for (int n = 0; n < NS; n++) {
        float a  = alpha[d * NS + n];
        float de = delta[d * NS + n];
        float g0 = gamma[(d * NS + n) * 2 + 0];
        float g1 = gamma[(d * NS + n) * 2 + 1];
        float p  = 1.0f / (1.0f + expf(-a));
        float dd = 1.0f / (1.0f + expf(-de));
        float phi = (float)(n + 1) * base;
        float mag = 1.0f - p * dd;
        float s, c;
        sincosf(phi, &s, &c);
        qr[n] = mag * c;
        qi[n] = mag * s;
        cr[n] = p * g0 * 0.25f;   // SCALE = sqrt(1/16) = 0.25 exactly
        ci[n] = p * g1 * 0.25f;
    }

    const size_t chbase = (size_t)warp * LL;
    const float4* __restrict__ xc4 =
        (const float4*)(x + chbase + (size_t)lane * CHUNK);

    // ---- Phase 1: local scan from zero state (no y) ----
    float Sr[NS], Si[NS];
    #pragma unroll
    for (int n = 0; n < NS; n++) { Sr[n] = 0.0f; Si[n] = 0.0f; }

    #pragma unroll 1
    for (int i4 = 0; i4 < CHUNK / 4; i4++) {
        float4 xv = xc4[i4];
        float xs0 = xv.x, xs1 = xv.y, xs2 = xv.z, xs3 = xv.w;
        #pragma unroll
        for (int n = 0; n < NS; n++) {
            float sr = Sr[n], si = Si[n];
            float nr, ni;
            nr = fmaf(qr[n], sr, fmaf(-qi[n], si, xs0));
            ni = fmaf(qr[n], si, qi[n] * sr); sr = nr; si = ni;
            nr = fmaf(qr[n], sr, fmaf(-qi[n], si, xs1));
            ni = fmaf(qr[n], si, qi[n] * sr); sr = nr; si = ni;
            nr = fmaf(qr[n], sr, fmaf(-qi[n], si, xs2));
            ni = fmaf(qr[n], si, qi[n] * sr); sr = nr; si = ni;
            nr = fmaf(qr[n], sr, fmaf(-qi[n], si, xs3));
            ni = fmaf(qr[n], si, qi[n] * sr);
            Sr[n] = nr; Si[n] = ni;
        }
    }

    // ---- A = q^CHUNK by repeated squaring (CHUNK = 2^7) ----
    float Ar[NS], Ai[NS];
    #pragma unroll
    for (int n = 0; n < NS; n++) { Ar[n] = qr[n]; Ai[n] = qi[n]; }
    #pragma unroll
    for (int s = 0; s < 7; s++) {
        #pragma unroll
        for (int n = 0; n < NS; n++) {
            float nr = fmaf(Ar[n], Ar[n], -Ai[n] * Ai[n]);
            float ni = 2.0f * Ar[n] * Ai[n];
            Ar[n] = nr; Ai[n] = ni;
        }
    }

    // ---- inclusive Hillis-Steele scan across 32 lanes:
    //      S_j <- A_k * S_{j-2^k} + S_j,  A_{k+1} = A_k^2 ----
    #pragma unroll
    for (int k = 1; k <= 16; k <<= 1) {
        #pragma unroll
        for (int n = 0; n < NS; n++) {
            float tr = __shfl_up_sync(0xFFFFFFFFu, Sr[n], k);
            float ti = __shfl_up_sync(0xFFFFFFFFu, Si[n], k);
            if (lane >= k) {
                float nr = fmaf(Ar[n], tr, fmaf(-Ai[n], ti, Sr[n]));
                float ni = fmaf(Ar[n], ti, fmaf(Ai[n], tr, Si[n]));
                Sr[n] = nr; Si[n] = ni;
            }
        }
        if (k < 16) {
            #pragma unroll
            for (int n = 0; n < NS; n++) {
                float nr = fmaf(Ar[n], Ar[n], -Ai[n] * Ai[n]);
                float ni = 2.0f * Ar[n] * Ai[n];
                Ar[n] = nr; Ai[n] = ni;
            }
        }
    }

    // ---- h output from lane 31 (full inclusive scan):
    //      h = p * S[L-1]; recompute p from alpha to save registers ----
    if (lane == 31) {
        float* hptr = out + (size_t)BB * DD * LL + ((size_t)warp * NS) * 2;
        #pragma unroll
        for (int n = 0; n < NS; n++) {
            float p = 1.0f / (1.0f + expf(-alpha[d * NS + n]));
            hptr[2 * n + 0] = p * Sr[n];
            hptr[2 * n + 1] = p * Si[n];
        }
    }

    // ---- incoming state for each chunk = exclusive scan (shift by 1) ----
    #pragma unroll
    for (int n = 0; n < NS; n++) {
        float tr = __shfl_up_sync(0xFFFFFFFFu, Sr[n], 1);
        float ti = __shfl_up_sync(0xFFFFFFFFu, Si[n], 1);
        Sr[n] = (lane == 0) ? 0.0f : tr;
        Si[n] = (lane == 0) ? 0.0f : ti;
    }

    // ---- Phase 2: rescan with correct init, emit y ----
    float4* __restrict__ yc4 = (float4*)(out + chbase + (size_t)lane * CHUNK);
    #pragma unroll 1
    for (int i4 = 0; i4 < CHUNK / 4; i4++) {
        float4 xv = xc4[i4];
        float xs[4] = { xv.x, xv.y, xv.z, xv.w };
        float ys[4];
        #pragma unroll
        for (int k = 0; k < 4; k++) {
            float xk = xs[k];
            float acc = xk * om;
            #pragma unroll
            for (int n = 0; n < NS; n++) {
                float nr = fmaf(qr[n], Sr[n], fmaf(-qi[n], Si[n], xk));
                float ni = fmaf(qr[n], Si[n], qi[n] * Sr[n]);
                Sr[n] = nr; Si[n] = ni;
                acc = fmaf(cr[n], nr, acc);
                acc = fmaf(-ci[n], ni, acc);
            }
            ys[k] = acc;
        }
        yc4[i4] = make_float4(ys[0], ys[1], ys[2], ys[3]);
    }
}

extern "C" void kernel_launch(void* const* d_in, const int* in_sizes, int n_in,
                              void* d_out, int out_size)
{
    const float* x     = (const float*)d_in[0];
    const float* alpha = (const float*)d_in[1];
    const float* delta = (const float*)d_in[2];
    const float* theta = (const float*)d_in[3];
    const float* gamma = (const float*)d_in[4];
    const float* omega = (const float*)d_in[5];
    float* out = (float*)d_out;

    const int threads = 256;                       // 8 warps/block
    const int blocks  = (NCHAN * 32) / threads;    // 512 blocks
    cema_kernel<<<blocks, threads>>>(x, alpha, delta, theta, gamma, omega, out);
}

// round 2
// speedup vs baseline: 1.1335x; 1.1335x over previous
#include <cuda_runtime.h>
#include <math.h>

#define DD     2048
#define NS     16
#define NP     8               // packed mode pairs
#define BB     2
#define LL     4096
#define NCHAN  (BB * DD)
#define CHUNK  (LL / 32)

typedef unsigned long long u64;

__device__ __forceinline__ u64 pk2(float lo, float hi) {
    u64 r; asm("mov.b64 %0, {%1,%2};" : "=l"(r) : "f"(lo), "f"(hi)); return r;
}
__device__ __forceinline__ void upk2(u64 v, float& lo, float& hi) {
    asm("mov.b64 {%0,%1}, %2;" : "=f"(lo), "=f"(hi) : "l"(v));
}
__device__ __forceinline__ u64 ffma2(u64 a, u64 b, u64 c) {
    u64 d; asm("fma.rn.f32x2 %0, %1, %2, %3;" : "=l"(d) : "l"(a), "l"(b), "l"(c)); return d;
}
__device__ __forceinline__ u64 fmul2(u64 a, u64 b) {
    u64 d; asm("mul.rn.f32x2 %0, %1, %2;" : "=l"(d) : "l"(a), "l"(b)); return d;
}
__device__ __forceinline__ u64 fadd2(u64 a, u64 b) {
    u64 d; asm("add.rn.f32x2 %0, %1, %2;" : "=l"(d) : "l"(a), "l"(b)); return d;
}
__device__ __forceinline__ float sigm(float v) {
    return 1.0f / (1.0f + expf(-v));
}

__global__ __launch_bounds__(256) void cema_kernel(
    const float* __restrict__ x,      // (B, D, L)
    const float* __restrict__ alpha,  // (D, N)
    const float* __restrict__ delta,  // (D, N)
    const float* __restrict__ theta,  // (D)
    const float* __restrict__ gamma,  // (D, N, 2)
    const float* __restrict__ omega,  // (D)
    float* __restrict__ out)          // y (B,D,L) then h (B,D,N,2)
{
    const int warp = (blockIdx.x * blockDim.x + threadIdx.x) >> 5;
    const int lane = threadIdx.x & 31;
    if (warp >= NCHAN) return;
    const int d = warp & (DD - 1);

    // ---- per-channel q coefficients, packed over mode pairs ----
    u64 Qr[NP], Qi[NP], nQi[NP];
    const float base = sigm(theta[d]) * (6.283185307179586f / 16.0f);
    const float om   = omega[d];
    #pragma unroll
    for (int j = 0; j < NP; j++) {
        float qr2[2], qi2[2];
        #pragma unroll
        for (int h = 0; h < 2; h++) {
            int n = 2 * j + h;
            float p  = sigm(alpha[d * NS + n]);
            float de = sigm(delta[d * NS + n]);
            float mag = 1.0f - p * de;
            float s, c;
            sincosf((float)(n + 1) * base, &s, &c);
            qr2[h] = mag * c;
            qi2[h] = mag * s;
        }
        Qr[j]  = pk2(qr2[0], qr2[1]);
        Qi[j]  = pk2(qi2[0], qi2[1]);
        nQi[j] = pk2(-qi2[0], -qi2[1]);
    }

    const size_t chbase = (size_t)warp * LL;
    const float4* __restrict__ xc4 =
        (const float4*)(x + chbase + (size_t)lane * CHUNK);

    // ---- Phase 1: local scan from zero state ----
    u64 Sr[NP], Si[NP];
    #pragma unroll
    for (int j = 0; j < NP; j++) { Sr[j] = 0ull; Si[j] = 0ull; }

    #pragma unroll 1
    for (int i4 = 0; i4 < CHUNK / 4; i4++) {
        float4 xv = xc4[i4];
        float xs[4] = { xv.x, xv.y, xv.z, xv.w };
        #pragma unroll
        for (int k = 0; k < 4; k++) {
            u64 X = pk2(xs[k], xs[k]);
            #pragma unroll
            for (int j = 0; j < NP; j++) {
                u64 nr = ffma2(Qr[j], Sr[j], ffma2(nQi[j], Si[j], X));
                u64 ni = ffma2(Qr[j], Si[j], fmul2(Qi[j], Sr[j]));
                Sr[j] = nr; Si[j] = ni;
            }
        }
    }

    // ---- A = q^CHUNK by repeated squaring (CHUNK = 2^7) ----
    u64 Ar[NP], Ai[NP], nAi[NP];
    const u64 NEG1 = pk2(-1.0f, -1.0f);
    #pragma unroll
    for (int j = 0; j < NP; j++) { Ar[j] = Qr[j]; Ai[j] = Qi[j]; nAi[j] = nQi[j]; }
    #pragma unroll
    for (int s = 0; s < 7; s++) {
        #pragma unroll
        for (int j = 0; j < NP; j++) {
            u64 nr = ffma2(nAi[j], Ai[j], fmul2(Ar[j], Ar[j]));
            u64 ni = fmul2(fadd2(Ar[j], Ar[j]), Ai[j]);
            Ar[j] = nr; Ai[j] = ni; nAi[j] = fmul2(ni, NEG1);
        }
    }

    // ---- inclusive Hillis-Steele scan across 32 lanes ----
    #pragma unroll
    for (int k = 1; k <= 16; k <<= 1) {
        #pragma unroll
        for (int j = 0; j < NP; j++) {
            u64 tr = __shfl_up_sync(0xFFFFFFFFu, Sr[j], k);
            u64 ti = __shfl_up_sync(0xFFFFFFFFu, Si[j], k);
            if (lane >= k) {
                u64 nr = ffma2(Ar[j], tr, ffma2(nAi[j], ti, Sr[j]));
                u64 ni = ffma2(Ar[j], ti, ffma2(Ai[j], tr, Si[j]));
                Sr[j] = nr; Si[j] = ni;
            }
        }
        if (k < 16) {
            #pragma unroll
            for (int j = 0; j < NP; j++) {
                u64 nr = ffma2(nAi[j], Ai[j], fmul2(Ar[j], Ar[j]));
                u64 ni = fmul2(fadd2(Ar[j], Ar[j]), Ai[j]);
                Ar[j] = nr; Ai[j] = ni; nAi[j] = fmul2(ni, NEG1);
            }
        }
    }

    // ---- h output from lane 31: h = p * S[L-1] ----
    if (lane == 31) {
        float* hptr = out + (size_t)BB * DD * LL + ((size_t)warp * NS) * 2;
        #pragma unroll
        for (int j = 0; j < NP; j++) {
            float sr0, sr1, si0, si1;
            upk2(Sr[j], sr0, sr1);
            upk2(Si[j], si0, si1);
            float p0 = sigm(alpha[d * NS + 2 * j + 0]);
            float p1 = sigm(alpha[d * NS + 2 * j + 1]);
            hptr[4 * j + 0] = p0 * sr0;
            hptr[4 * j + 1] = p0 * si0;
            hptr[4 * j + 2] = p1 * sr1;
            hptr[4 * j + 3] = p1 * si1;
        }
    }

    // ---- incoming state per chunk = exclusive scan (shift by 1) ----
    #pragma unroll
    for (int j = 0; j < NP; j++) {
        u64 tr = __shfl_up_sync(0xFFFFFFFFu, Sr[j], 1);
        u64 ti = __shfl_up_sync(0xFFFFFFFFu, Si[j], 1);
        Sr[j] = (lane == 0) ? 0ull : tr;
        Si[j] = (lane == 0) ? 0ull : ti;
    }

    // ---- output coefficients (computed late to trim live ranges) ----
    u64 Cr[NP], nCi[NP];
    #pragma unroll
    for (int j = 0; j < NP; j++) {
        float cr2[2], ci2[2];
        #pragma unroll
        for (int h = 0; h < 2; h++) {
            int n = 2 * j + h;
            float p  = sigm(alpha[d * NS + n]);
            float g0 = gamma[(d * NS + n) * 2 + 0];
            float g1 = gamma[(d * NS + n) * 2 + 1];
            cr2[h] = p * g0 * 0.25f;   // SCALE = 0.25 exactly
            ci2[h] = p * g1 * 0.25f;
        }
        Cr[j]  = pk2(cr2[0], cr2[1]);
        nCi[j] = pk2(-ci2[0], -ci2[1]);
    }

    // ---- Phase 2: rescan with correct init, emit y ----
    float4* __restrict__ yc4 = (float4*)(out + chbase + (size_t)lane * CHUNK);
    #pragma unroll 1
    for (int i4 = 0; i4 < CHUNK / 4; i4++) {
        float4 xv = xc4[i4];
        float xs[4] = { xv.x, xv.y, xv.z, xv.w };
        float ys[4];
        #pragma unroll
        for (int k = 0; k < 4; k++) {
            float xk = xs[k];
            u64 X = pk2(xk, xk);
            u64 acc0 = pk2(xk * om, 0.0f);
            u64 acc1 = 0ull, acc2 = 0ull, acc3 = 0ull;
            #pragma unroll
            for (int j = 0; j < NP; j++) {
                u64 nr = ffma2(Qr[j], Sr[j], ffma2(nQi[j], Si[j], X));
                u64 ni = ffma2(Qr[j], Si[j], fmul2(Qi[j], Sr[j]));
                Sr[j] = nr; Si[j] = ni;
                u64& acc = (j & 3) == 0 ? acc0 : (j & 3) == 1 ? acc1
                         : (j & 3) == 2 ? acc2 : acc3;
                acc = ffma2(Cr[j], nr, acc);
                acc = ffma2(nCi[j], ni, acc);
            }
            u64 s = fadd2(fadd2(acc0, acc1), fadd2(acc2, acc3));
            float lo, hi;
            upk2(s, lo, hi);
            ys[k] = lo + hi;
        }
        yc4[i4] = make_float4(ys[0], ys[1], ys[2], ys[3]);
    }
}

extern "C" void kernel_launch(void* const* d_in, const int* in_sizes, int n_in,
                              void* d_out, int out_size)
{
    const float* x     = (const float*)d_in[0];
    const float* alpha = (const float*)d_in[1];
    const float* delta = (const float*)d_in[2];
    const float* theta = (const float*)d_in[3];
    const float* gamma = (const float*)d_in[4];
    const float* omega = (const float*)d_in[5];
    float* out = (float*)d_out;

    const int threads = 256;
    const int blocks  = (NCHAN * 32) / threads;
    cema_kernel<<<blocks, threads>>>(x, alpha, delta, theta, gamma, omega, out);
}